// round 13
// baseline (speedup 1.0000x reference)
#include <cuda_runtime.h>
#include <cstdint>

// CASSI forward: half-row blocks, 3-deep TMA ring, LDG-seeded halo carry.
//
// Grid (2, 1024): block (h, m) computes y[m, c], h=0: c in [0,512),
// h=1: c in [512,1087). h=1 seeds its diagonal carry with direct LDGs
// over the 63 halo rows (coalesced in tid at each k; ca read is a lane-
// uniform broadcast) -- no halo smem, so a 3-deep 96KB TMA ring still
// fits 2 blocks/SM (98.3KB/block).
// Per tile (TN=128 n-rows, 32KB): thread tid accumulates
//   accL -> output c = n0 + t*128 + tid  (terms l <= tid)
//   accH -> carry for next tile          (terms l >  tid)

#define MM    1024
#define NN    1024
#define LL    64
#define OUTC  (NN + LL - 1)            // 1087
#define TN    128
#define TPB   128
#define HALF  512
#define NTIL  (HALF / TN)              // 4
#define NBUF  3
#define TILE_BYTES (TN * LL * 4)       // 32768
#define HALO_ROWS  (LL - 1)            // 63

__device__ __forceinline__ uint32_t smem_u32(const void* p)
{
    uint32_t a;
    asm("{ .reg .u64 t; cvta.to.shared.u64 t, %1; cvt.u32.u64 %0, t; }"
        : "=r"(a) : "l"(p));
    return a;
}

__device__ __forceinline__ void mbar_init(uint32_t mb, uint32_t count)
{
    asm volatile("mbarrier.init.shared.b64 [%0], %1;" :: "r"(mb), "r"(count) : "memory");
}

__device__ __forceinline__ void tma_bulk(uint32_t dst, const float* src,
                                         uint32_t bytes, uint32_t mb)
{
    asm volatile("mbarrier.arrive.expect_tx.shared.b64 _, [%0], %1;"
                 :: "r"(mb), "r"(bytes) : "memory");
    asm volatile("cp.async.bulk.shared::cta.global.mbarrier::complete_tx::bytes "
                 "[%0], [%1], %2, [%3];"
                 :: "r"(dst), "l"(src), "r"(bytes), "r"(mb) : "memory");
}

__device__ __forceinline__ void mbar_wait(uint32_t mb, uint32_t parity)
{
    uint32_t done;
    asm volatile(
        "{\n\t"
        ".reg .pred p;\n\t"
        "mbarrier.try_wait.parity.acquire.cta.shared::cta.b64 p, [%1], %2;\n\t"
        "selp.b32 %0, 1, 0, p;\n\t"
        "}"
        : "=r"(done) : "r"(mb), "r"(parity) : "memory");
    if (!done) {
        asm volatile(
            "{\n\t"
            ".reg .pred P1;\n\t"
            "W%=:\n\t"
            "mbarrier.try_wait.parity.acquire.cta.shared::cta.b64 P1, [%0], %1;\n\t"
            "@P1 bra D%=;\n\t"
            "bra W%=;\n\t"
            "D%=:\n\t"
            "}"
            :: "r"(mb), "r"(parity) : "memory");
    }
}

__global__ __launch_bounds__(TPB)
void cassi_ring3_kernel(const float* __restrict__ x,
                        const float* __restrict__ ca,
                        float* __restrict__ y)
{
    extern __shared__ float smem[];
    float* bufs = smem;                          // NBUF * 8192 floats (96KB)
    float* sca  = bufs + NBUF * TN * LL;         // 512 floats
    __shared__ __align__(8) uint64_t mbar_store[NBUF];

    const int m   = blockIdx.y;
    const int h   = blockIdx.x;                  // 0 or 1
    const int n0  = h * HALF;
    const int tid = threadIdx.x;

    const float* xbase = x + (size_t)m * (NN * LL);
    const float* xrow  = xbase + (size_t)n0 * LL;
    const float* carow = ca + m * NN;
    float*       yrow  = y + (size_t)m * OUTC;

    uint32_t mb[NBUF], bs[NBUF];
    #pragma unroll
    for (int i = 0; i < NBUF; ++i) {
        mb[i] = smem_u32(&mbar_store[i]);
        bs[i] = smem_u32(bufs + i * TN * LL);
    }

    if (tid == 0) {
        #pragma unroll
        for (int i = 0; i < NBUF; ++i) mbar_init(mb[i], 1);
    }
    __syncthreads();

    if (tid == 0) {
        #pragma unroll
        for (int i = 0; i < NBUF; ++i)
            tma_bulk(bs[i], xrow + (size_t)i * TN * LL, TILE_BYTES, mb[i]);
    }

    // Stage ca for this half (one float4 per thread).
    {
        float4* s4 = (float4*)sca;
        const float4* c4 = (const float4*)(carow + n0);
        s4[tid] = c4[tid];
    }

    // Seed carry for h=1 via direct LDGs over the halo rows:
    //   carry[tid] = sum_{k=tid}^{62} x[m][n0-63+k][63+tid-k] * ca[m][n0-63+k]
    // At fixed k the x-read is consecutive in tid (coalesced); the ca-read
    // is lane-uniform (broadcast). Overlaps with the in-flight tile-0 TMA.
    float carry = 0.0f;
    if (h == 1 && tid < HALO_ROWS) {
        const float* xh  = xbase + (size_t)(n0 - HALO_ROWS) * LL;
        const float* cah = carow + (n0 - HALO_ROWS);
        #pragma unroll
        for (int k = 0; k < HALO_ROWS; ++k) {
            if (k >= tid)
                carry = fmaf(__ldg(xh + (size_t)k * LL + (HALO_ROWS + tid - k)),
                             __ldg(cah + k), carry);
        }
    }
    __syncthreads();   // sca visible to all

    #pragma unroll 1
    for (int t = 0; t < NTIL; ++t) {
        const int      b      = (t < NBUF) ? t : t - NBUF;
        const uint32_t parity = (t < NBUF) ? 0u : 1u;
        const float*   cur    = bufs + b * TN * LL;

        mbar_wait(mb[b], parity);

        const float* scat = sca + t * TN;
        float accL = carry;                  // carry == 0 for tid >= LL-1
        float accH = 0.0f;
        #pragma unroll
        for (int j = 0; j < LL; ++j) {
            const int  l   = (tid + j) & (LL - 1);
            const bool low = (l <= tid);
            const int  n   = low ? (tid - l) : (tid + TN - l);
            const float v  = cur[n * LL + l];
            if (low) accL = fmaf(v, scat[n], accL);
            else     accH = fmaf(v, scat[n], accH);
        }
        yrow[n0 + t * TN + tid] = accL;
        carry = accH;

        __syncthreads();                     // all threads done reading `cur`

        if (tid == 0 && t + NBUF < NTIL)
            tma_bulk(bs[b], xrow + (size_t)(t + NBUF) * TN * LL,
                     TILE_BYTES, mb[b]);
    }

    // Tail: h=1 writes c in [NN, NN+LL-1); h=0's final carry is discarded
    // (those columns are fully computed by h=1 via the halo seed).
    if (h == 1 && tid < LL - 1)
        yrow[NN + tid] = carry;
}

extern "C" void kernel_launch(void* const* d_in, const int* in_sizes, int n_in,
                              void* d_out, int out_size)
{
    const float* x  = (const float*)d_in[0];
    const float* ca = (const float*)d_in[1];
    float* y        = (float*)d_out;

    const int smem_bytes = (NBUF * TN * LL + HALF) * sizeof(float);  // 100352 B

    cudaFuncSetAttribute(cassi_ring3_kernel,
                         cudaFuncAttributeMaxDynamicSharedMemorySize,
                         smem_bytes);

    cassi_ring3_kernel<<<dim3(2, MM), TPB, smem_bytes>>>(x, ca, y);
}

// round 14
// speedup vs baseline: 1.2045x; 1.2045x over previous
#include <cuda_runtime.h>
#include <cstdint>

// CASSI forward: half-row blocks, 3-deep TMA ring sharing smem with the
// halo tile (R12 body + deeper queue, zero extra smem).
//
// Grid (2, 1024): block (h, m) computes y[m, c]; h=0: c in [0,512),
// h=1: c in [512,1087). h=1 seeds its diagonal carry from a 63-row halo
// tile TMA'd into buf2 (which tile 2 reuses afterwards). smem = 3*32KB
// ring + 2.3KB ca = 98.3KB -> 2 blocks/SM.
// Per tile (TN=128 n-rows): thread tid accumulates
//   accL -> output c = n0 + t*128 + tid  (terms l <= tid)
//   accH -> carry for next tile          (terms l >  tid)

#define MM    1024
#define NN    1024
#define LL    64
#define OUTC  (NN + LL - 1)            // 1087
#define TN    128
#define TPB   128
#define HALF  512
#define NTIL  (HALF / TN)              // 4
#define NBUF  3
#define TILE_BYTES (TN * LL * 4)       // 32768
#define HALO_ROWS  (LL - 1)            // 63
#define HALO_BYTES (HALO_ROWS * LL * 4)  // 16128

__device__ __forceinline__ uint32_t smem_u32(const void* p)
{
    uint32_t a;
    asm("{ .reg .u64 t; cvta.to.shared.u64 t, %1; cvt.u32.u64 %0, t; }"
        : "=r"(a) : "l"(p));
    return a;
}

__device__ __forceinline__ void mbar_init(uint32_t mb, uint32_t count)
{
    asm volatile("mbarrier.init.shared.b64 [%0], %1;" :: "r"(mb), "r"(count) : "memory");
}

__device__ __forceinline__ void tma_bulk(uint32_t dst, const float* src,
                                         uint32_t bytes, uint32_t mb)
{
    asm volatile("mbarrier.arrive.expect_tx.shared.b64 _, [%0], %1;"
                 :: "r"(mb), "r"(bytes) : "memory");
    asm volatile("cp.async.bulk.shared::cta.global.mbarrier::complete_tx::bytes "
                 "[%0], [%1], %2, [%3];"
                 :: "r"(dst), "l"(src), "r"(bytes), "r"(mb) : "memory");
}

__device__ __forceinline__ void mbar_wait(uint32_t mb, uint32_t parity)
{
    uint32_t done;
    asm volatile(
        "{\n\t"
        ".reg .pred p;\n\t"
        "mbarrier.try_wait.parity.acquire.cta.shared::cta.b64 p, [%1], %2;\n\t"
        "selp.b32 %0, 1, 0, p;\n\t"
        "}"
        : "=r"(done) : "r"(mb), "r"(parity) : "memory");
    if (!done) {
        asm volatile(
            "{\n\t"
            ".reg .pred P1;\n\t"
            "W%=:\n\t"
            "mbarrier.try_wait.parity.acquire.cta.shared::cta.b64 P1, [%0], %1;\n\t"
            "@P1 bra D%=;\n\t"
            "bra W%=;\n\t"
            "D%=:\n\t"
            "}"
            :: "r"(mb), "r"(parity) : "memory");
    }
}

__global__ __launch_bounds__(TPB)
void cassi_ring3h_kernel(const float* __restrict__ x,
                         const float* __restrict__ ca,
                         float* __restrict__ y)
{
    extern __shared__ float smem[];
    float* bufs = smem;                          // NBUF * 8192 floats (96KB)
    float* sca  = bufs + NBUF * TN * LL;         // 512 floats
    float* scah = sca + HALF;                    // 64 floats
    __shared__ __align__(8) uint64_t mbar_store[NBUF + 1];

    const int m   = blockIdx.y;
    const int h   = blockIdx.x;                  // 0 or 1
    const int n0  = h * HALF;
    const int tid = threadIdx.x;

    const float* xbase = x + (size_t)m * (NN * LL);
    const float* xrow  = xbase + (size_t)n0 * LL;
    const float* carow = ca + m * NN;
    float*       yrow  = y + (size_t)m * OUTC;

    uint32_t mb[NBUF + 1], bs[NBUF];
    #pragma unroll
    for (int i = 0; i < NBUF + 1; ++i) mb[i] = smem_u32(&mbar_store[i]);
    #pragma unroll
    for (int i = 0; i < NBUF; ++i) bs[i] = smem_u32(bufs + i * TN * LL);

    if (tid == 0) {
        #pragma unroll
        for (int i = 0; i < NBUF + 1; ++i) mbar_init(mb[i], 1);
    }
    __syncthreads();

    if (tid == 0) {
        tma_bulk(bs[0], xrow,               TILE_BYTES, mb[0]);
        tma_bulk(bs[1], xrow + 1 * TN * LL, TILE_BYTES, mb[1]);
        if (h == 0)
            tma_bulk(bs[2], xrow + 2 * TN * LL, TILE_BYTES, mb[2]);
        else
            // halo (n in [449,512)) lands in buf2; tile2 reuses it later
            tma_bulk(bs[2], xbase + (size_t)(n0 - HALO_ROWS) * LL,
                     HALO_BYTES, mb[NBUF]);
    }

    // Stage ca for this half (+ halo ca for h=1).
    {
        float4* s4 = (float4*)sca;
        const float4* c4 = (const float4*)(carow + n0);
        s4[tid] = c4[tid];
    }
    if (h == 1 && tid < HALO_ROWS)
        scah[tid] = carow[(n0 - HALO_ROWS) + tid];
    __syncthreads();

    // Seed carry for h=1 from the halo tile (buf2):
    //   carry[tid] = sum_{k=tid}^{62} halo[k][63+tid-k] * scah[k]
    float carry = 0.0f;
    if (h == 1) {
        mbar_wait(mb[NBUF], 0);
        const float* halo = bufs + 2 * TN * LL;
        if (tid < HALO_ROWS) {
            #pragma unroll
            for (int k = 0; k < HALO_ROWS; ++k) {
                if (k >= tid)
                    carry = fmaf(halo[k * LL + (HALO_ROWS + tid - k)], scah[k], carry);
            }
        }
        __syncthreads();          // all threads done reading buf2
        if (tid == 0)             // now safe to overwrite buf2 with tile 2
            tma_bulk(bs[2], xrow + 2 * TN * LL, TILE_BYTES, mb[2]);
    }

    #pragma unroll 1
    for (int t = 0; t < NTIL; ++t) {
        const int      b      = (t < NBUF) ? t : t - NBUF;
        const uint32_t parity = (t < NBUF) ? 0u : 1u;
        const float*   cur    = bufs + b * TN * LL;

        mbar_wait(mb[b], parity);

        const float* scat = sca + t * TN;
        float accL = carry;                  // carry == 0 for tid >= LL-1
        float accH = 0.0f;
        #pragma unroll
        for (int j = 0; j < LL; ++j) {
            const int  l   = (tid + j) & (LL - 1);
            const bool low = (l <= tid);
            const int  n   = low ? (tid - l) : (tid + TN - l);
            const float v  = cur[n * LL + l];
            if (low) accL = fmaf(v, scat[n], accL);
            else     accH = fmaf(v, scat[n], accH);
        }
        yrow[n0 + t * TN + tid] = accL;
        carry = accH;

        __syncthreads();                     // all threads done reading `cur`

        if (tid == 0 && t + NBUF < NTIL)
            tma_bulk(bs[b], xrow + (size_t)(t + NBUF) * TN * LL,
                     TILE_BYTES, mb[b]);
    }

    // Tail: h=1 writes c in [NN, NN+LL-1); h=0's final carry is discarded
    // (those columns are fully computed by h=1 via the halo seed).
    if (h == 1 && tid < LL - 1)
        yrow[NN + tid] = carry;
}

extern "C" void kernel_launch(void* const* d_in, const int* in_sizes, int n_in,
                              void* d_out, int out_size)
{
    const float* x  = (const float*)d_in[0];
    const float* ca = (const float*)d_in[1];
    float* y        = (float*)d_out;

    const int smem_bytes =
        (NBUF * TN * LL + HALF + 64) * sizeof(float);   // 100608 B

    cudaFuncSetAttribute(cassi_ring3h_kernel,
                         cudaFuncAttributeMaxDynamicSharedMemorySize,
                         smem_bytes);

    cassi_ring3h_kernel<<<dim3(2, MM), TPB, smem_bytes>>>(x, ca, y);
}